// round 2
// baseline (speedup 1.0000x reference)
#include <cuda_runtime.h>
#include <cstdint>

// inputs: (B=8, H=160, W=160, C=256) fp32 NHWC
// rois:   (N=1024, 5) fp32 [img_id, x0, y0, x1, y1]
// im_info:(N, 2) fp32 [H_img, W_img]
// output: (N, 7, 7, 256) fp32 = crop_and_resize(14x14 bilinear) -> maxpool 2x2 s2
// Fused: each pooled pixel = max over 4 crop pixels, each crop pixel = 4-tap bilinear.

#define FEAT_H 160
#define FEAT_W 160
#define FEAT_C 256
#define CROP   14
#define POOL   7

__device__ __forceinline__ void stcs_f2(float2* p, float2 v) {
    asm volatile("st.global.cs.v2.f32 [%0], {%1, %2};" :: "l"(p), "f"(v.x), "f"(v.y) : "memory");
}

__global__ __launch_bounds__(128)
void roipool_kernel(const float* __restrict__ in,
                    const float* __restrict__ rois,
                    const float* __restrict__ im_info,
                    float* __restrict__ out)
{
    const int blk = blockIdx.x;            // roi * 49 + pooled_pixel
    const int roi = blk / 49;
    const int pix = blk - roi * 49;
    const int py  = pix / POOL;
    const int px  = pix - py * POOL;
    const int t   = threadIdx.x;           // 0..127, float2 channel lane

    // --- ROI parameters (warp-uniform broadcast loads) ---
    const float b_f   = __ldg(&rois[roi * 5 + 0]);
    const float H_img = __ldg(&im_info[roi * 2 + 0]);
    const float W_img = __ldg(&im_info[roi * 2 + 1]);
    const float x1 = __ldg(&rois[roi * 5 + 1]) / W_img;
    const float y1 = __ldg(&rois[roi * 5 + 2]) / H_img;
    const float x2 = __ldg(&rois[roi * 5 + 3]) / W_img;
    const float y2 = __ldg(&rois[roi * 5 + 4]) / H_img;
    const int   b  = (int)b_f;

    // Reference arithmetic order: y1*(Hf-1) + iy * ((y2-y1)*(Hf-1)/(ch-1))
    const float Hm1 = (float)(FEAT_H - 1);
    const float Wm1 = (float)(FEAT_W - 1);
    const float sy = (y2 - y1) * Hm1 / (float)(CROP - 1);
    const float sx = (x2 - x1) * Wm1 / (float)(CROP - 1);
    const float by = y1 * Hm1;
    const float bx = x1 * Wm1;

    // --- coords for the 2x2 crop pixels feeding this pooled pixel ---
    float ylp[2], xlp[2];
    int   yl[2], yh[2], xl[2], xh[2];
    bool  vy[2], vx[2];

    #pragma unroll
    for (int i = 0; i < 2; ++i) {
        const float y = by + (float)(2 * py + i) * sy;
        vy[i]  = (y >= 0.0f) && (y <= Hm1);
        const float yf = floorf(y);
        ylp[i] = y - yf;
        yl[i]  = min(max((int)yf, 0), FEAT_H - 1);
        yh[i]  = min(max((int)yf + 1, 0), FEAT_H - 1);

        const float x = bx + (float)(2 * px + i) * sx;
        vx[i]  = (x >= 0.0f) && (x <= Wm1);
        const float xf = floorf(x);
        xlp[i] = x - xf;
        xl[i]  = min(max((int)xf, 0), FEAT_W - 1);
        xh[i]  = min(max((int)xf + 1, 0), FEAT_W - 1);
    }

    // --- batch ALL 16 tap loads (max MLP, one latency exposure) ---
    // float2 lane layout: base + cell*128 + t   (128 float2 per spatial cell)
    const float2* __restrict__ base = (const float2*)in + t;
    const int rb = b * (FEAT_H * FEAT_W);

    float2 v[16];
    #pragma unroll
    for (int iy = 0; iy < 2; ++iy) {
        #pragma unroll
        for (int ix = 0; ix < 2; ++ix) {
            const int rl = rb + yl[iy] * FEAT_W;
            const int rh = rb + yh[iy] * FEAT_W;
            const int k = (iy * 2 + ix) * 4;
            v[k + 0] = __ldg(base + (size_t)(rl + xl[ix]) * (FEAT_C / 2));  // tl
            v[k + 1] = __ldg(base + (size_t)(rl + xh[ix]) * (FEAT_C / 2));  // tr
            v[k + 2] = __ldg(base + (size_t)(rh + xl[ix]) * (FEAT_C / 2));  // bl
            v[k + 3] = __ldg(base + (size_t)(rh + xh[ix]) * (FEAT_C / 2));  // br
        }
    }

    // --- bilinear + mask + running max ---
    const float NEG_INF = __int_as_float(0xff800000);
    float2 vmax = make_float2(NEG_INF, NEG_INF);

    #pragma unroll
    for (int iy = 0; iy < 2; ++iy) {
        #pragma unroll
        for (int ix = 0; ix < 2; ++ix) {
            const int k = (iy * 2 + ix) * 4;
            const float yw = ylp[iy];
            const float xw = xlp[ix];
            const bool  ok = vy[iy] && vx[ix];
            const float2 tl = v[k + 0], tr = v[k + 1], bl = v[k + 2], br = v[k + 3];
            float top, bot, r0, r1;
            top = tl.x + (tr.x - tl.x) * xw;  bot = bl.x + (br.x - bl.x) * xw;  r0 = top + (bot - top) * yw;
            top = tl.y + (tr.y - tl.y) * xw;  bot = bl.y + (br.y - bl.y) * xw;  r1 = top + (bot - top) * yw;
            if (!ok) { r0 = 0.0f; r1 = 0.0f; }
            vmax.x = fmaxf(vmax.x, r0);
            vmax.y = fmaxf(vmax.y, r1);
        }
    }

    // streaming store: output is never re-read, keep it out of L2's way
    stcs_f2((float2*)out + (size_t)blk * (FEAT_C / 2) + t, vmax);
}

extern "C" void kernel_launch(void* const* d_in, const int* in_sizes, int n_in,
                              void* d_out, int out_size)
{
    const float* in      = (const float*)d_in[0];
    const float* rois    = (const float*)d_in[1];
    const float* im_info = (const float*)d_in[2];
    float* out           = (float*)d_out;

    const int N = in_sizes[1] / 5;   // 1024
    dim3 grid(N * POOL * POOL);      // 50176 blocks
    dim3 block(128);                 // 128 threads x float2 = 256 channels
    roipool_kernel<<<grid, block>>>(in, rois, im_info, out);
}